// round 14
// baseline (speedup 1.0000x reference)
#include <cuda_runtime.h>
#include <cuda_bf16.h>
#include <cstdint>
#include <math.h>

#define B_  32768
#define D_  768
#define H_  1024
#define L_  256
#define M_  32

// ---------------- helpers ----------------
__device__ __forceinline__ uint32_t smem_to_u32(const void* p) {
    uint32_t a;
    asm("{ .reg .u64 t; cvta.to.shared.u64 t, %1; cvt.u32.u64 %0, t; }" : "=r"(a) : "l"(p));
    return a;
}
__device__ __forceinline__ void cp16(uint32_t dst, const void* src) {
    asm volatile("cp.async.cg.shared.global [%0], [%1], 16;\n" :: "r"(dst), "l"(src) : "memory");
}
#define CP_COMMIT()  asm volatile("cp.async.commit_group;\n" ::: "memory")
#define CP_WAIT(n)   asm volatile("cp.async.wait_group %0;\n" :: "n"(n) : "memory")
#define LDMATRIX_X4(r0, r1, r2, r3, addr) \
    asm volatile("ldmatrix.sync.aligned.m8n8.x4.shared.b16 {%0,%1,%2,%3}, [%4];" \
                 : "=r"(r0), "=r"(r1), "=r"(r2), "=r"(r3) : "r"(addr))
#define MMA_S8(d, a, b0, b1) \
    asm volatile("mma.sync.aligned.m16n8k32.row.col.s32.s8.s8.s32 " \
                 "{%0,%1,%2,%3}, {%4,%5,%6,%7}, {%8,%9}, {%0,%1,%2,%3};" \
                 : "+r"((d)[0]), "+r"((d)[1]), "+r"((d)[2]), "+r"((d)[3]) \
                 : "r"((a)[0]), "r"((a)[1]), "r"((a)[2]), "r"((a)[3]), "r"(b0), "r"(b1))

// ---------------- scratch ----------------
#define WTOT 7340032
#define PMAX ((size_t)B_ * 2 * H_)
__device__ int8_t g_wqh[WTOT], g_wql[WTOT];
__device__ int8_t g_q1h[(size_t)B_ * 2048], g_q1l[(size_t)B_ * 2048];
__device__ int8_t g_q2h[(size_t)B_ * 2048], g_q2l[(size_t)B_ * 2048];
__device__ float g_f32[PMAX];
__device__ float g_sa1[B_], g_sa2[B_], g_ws[8192], g_bias512[512];

// quantize y into hi int8 (quantum sa) + lo int8 (quantum sa/256)
__device__ __forceinline__ void quant2(float y, float sa, float inv, float inv2,
                                       int8_t& h, int8_t& l) {
    int q = __float2int_rn(y * inv);
    float resid = y - sa * (float)q;
    int r = __float2int_rn(resid * inv2);
    r = r > 127 ? 127 : (r < -128 ? -128 : r);
    h = (int8_t)q;
    l = (int8_t)r;
}

// ---------------- block reductions ----------------
__device__ __forceinline__ float block_reduce_sum(float val, float* red) {
    const int lane = threadIdx.x & 31;
    const int w    = threadIdx.x >> 5;
    #pragma unroll
    for (int o = 16; o; o >>= 1) val += __shfl_xor_sync(0xffffffffu, val, o);
    if (lane == 0) red[w] = val;
    __syncthreads();
    float t = (lane < 8) ? red[lane] : 0.f;
    if (w == 0) {
        #pragma unroll
        for (int o = 4; o; o >>= 1) t += __shfl_xor_sync(0xffffffffu, t, o);
        if (lane == 0) red[0] = t;
    }
    __syncthreads();
    float r = red[0];
    __syncthreads();
    return r;
}
__device__ __forceinline__ float block_reduce_max(float val, float* red) {
    const int lane = threadIdx.x & 31;
    const int w    = threadIdx.x >> 5;
    #pragma unroll
    for (int o = 16; o; o >>= 1) val = fmaxf(val, __shfl_xor_sync(0xffffffffu, val, o));
    if (lane == 0) red[w] = val;
    __syncthreads();
    float t = (lane < 8) ? red[lane] : 0.f;
    if (w == 0) {
        #pragma unroll
        for (int o = 4; o; o >>= 1) t = fmaxf(t, __shfl_xor_sync(0xffffffffu, t, o));
        if (lane == 0) red[0] = t;
    }
    __syncthreads();
    float r = red[0];
    __syncthreads();
    return r;
}

// ---------------- generic row quantizer (one block per row) ----------------
__global__ __launch_bounds__(256)
void quant_rows_kernel(const float* __restrict__ X, int8_t* __restrict__ qh,
                       int8_t* __restrict__ ql, float* __restrict__ scale, int K) {
    const int row = blockIdx.x;
    const int tid = threadIdx.x;
    const float* xr = X + (size_t)row * K;
    __shared__ float red[8];

    float mx = 0.f;
    for (int i = tid; i < K / 4; i += 256) {
        float4 v = ((const float4*)xr)[i];
        mx = fmaxf(mx, fmaxf(fmaxf(fabsf(v.x), fabsf(v.y)), fmaxf(fabsf(v.z), fabsf(v.w))));
    }
    mx = block_reduce_max(mx, red);
    const float mxg  = fmaxf(mx, 1e-20f);
    const float sa   = mxg * (1.f / 127.f);
    const float inv  = 127.f / mxg;
    const float inv2 = 256.f * 127.f / mxg;
    if (tid == 0) scale[row] = sa;

    int8_t* qhr = qh + (size_t)row * K;
    int8_t* qlr = ql + (size_t)row * K;
    for (int i = tid; i < K / 4; i += 256) {
        float4 v = ((const float4*)xr)[i];
        int8_t h0, l0, h1, l1, h2, l2, h3, l3;
        quant2(v.x, sa, inv, inv2, h0, l0);
        quant2(v.y, sa, inv, inv2, h1, l1);
        quant2(v.z, sa, inv, inv2, h2, l2);
        quant2(v.w, sa, inv, inv2, h3, l3);
        ((char4*)qhr)[i] = make_char4(h0, h1, h2, h3);
        ((char4*)qlr)[i] = make_char4(l0, l1, l2, l3);
    }
}

// ---------------- int8 split GEMM via mma.sync (IMMA) ----------------
// C[B,N] = sa_r*sw_c*(hh + mid/256) + bias,  hh = Ah*Wh, mid = Ah*Wl + Al*Wh
// CTA 64x128, BK=64, 256 threads, warp tile 32x32 (warps 2m x 4n), occ 2.
#define ARR_A8   5120                  // 64 rows * 80B pitch
#define ARR_W8   10240                 // 128 rows * 80B
#define AW8_OFF  (2 * ARR_A8)          // 10240
#define STAGE8   (2 * ARR_A8 + 2 * ARR_W8)   // 30720
#define GSMEM    (2 * STAGE8)                // 61440

template<int OUT_MODE>   // 0: bias; 1: bias + lrelu. fp32 out.
__global__ void __launch_bounds__(256, 2)
imma_gemm_kernel(const int8_t* __restrict__ Aqh, const int8_t* __restrict__ Aql,
                 const float* __restrict__ scaleA,
                 const int8_t* __restrict__ Wqh, const int8_t* __restrict__ Wql,
                 const float* __restrict__ scaleW,
                 const float* __restrict__ bias, float* __restrict__ Cf,
                 int N, int K) {
    extern __shared__ char smem[];
    const uint32_t smem_u = smem_to_u32(smem);
    const int tid  = threadIdx.x;
    const int wid  = tid >> 5, lane = tid & 31;
    const int rowBase = blockIdx.y * 64;
    const int colBase = blockIdx.x * 128;
    const int warpM = wid & 1;      // 0..1 -> 32 rows
    const int warpN = wid >> 1;     // 0..3 -> 32 cols

    int acch[2][4][4], accm[2][4][4];
    #pragma unroll
    for (int t = 0; t < 2; t++)
        #pragma unroll
        for (int f = 0; f < 4; f++)
            #pragma unroll
            for (int e = 0; e < 4; e++) { acch[t][f][e] = 0; accm[t][f][e] = 0; }

    uint32_t aoff[2];
    #pragma unroll
    for (int t = 0; t < 2; t++)
        aoff[t] = (uint32_t)((warpM * 32 + t * 16 + (lane & 15)) * 80 + ((lane >> 4) << 4));
    uint32_t boff[2];
    #pragma unroll
    for (int g = 0; g < 2; g++) {
        int n = warpN * 32 + g * 16 + ((lane & 16) ? 8 : 0) + (lane & 7);
        boff[g] = (uint32_t)(AW8_OFF + n * 80 + ((lane & 8) ? 16 : 0));
    }

    const int ktiles = K >> 6;     // BK = 64

    auto fill = [&](int s, int kt) {
        const uint32_t stb = smem_u + s * STAGE8;
        const int kOff = kt * 64;
        #pragma unroll
        for (int it = 0; it < 2; it++) {          // A: 512 chunks (2 arrays)
            int idx = it * 256 + tid;
            int arr = idx >> 8;
            int rem = idx & 255;
            int r   = rem >> 2;
            int c   = rem & 3;
            const int8_t* src = (arr ? Aql : Aqh) + (size_t)(rowBase + r) * K + kOff + c * 16;
            cp16(stb + arr * ARR_A8 + r * 80 + c * 16, src);
        }
        #pragma unroll
        for (int it = 0; it < 4; it++) {          // W: 1024 chunks
            int idx = it * 256 + tid;
            int arr = idx >> 9;
            int rem = idx & 511;
            int r   = rem >> 2;
            int c   = rem & 3;
            const int8_t* src = (arr ? Wql : Wqh) + (size_t)(colBase + r) * K + kOff + c * 16;
            cp16(stb + AW8_OFF + arr * ARR_W8 + r * 80 + c * 16, src);
        }
        CP_COMMIT();
    };

    fill(0, 0);
    for (int kt = 0; kt < ktiles; kt++) {
        const int s = kt & 1;
        CP_WAIT(0);
        __syncthreads();
        if (kt + 1 < ktiles) fill(s ^ 1, kt + 1);

        const uint32_t stb = smem_u + s * STAGE8;
        #pragma unroll
        for (int kc = 0; kc < 2; kc++) {          // two k32 chunks
            const uint32_t kb = kc * 32;
            uint32_t ah[2][4], al[2][4], bh[2][4], bl[2][4];
            #pragma unroll
            for (int t = 0; t < 2; t++) {
                LDMATRIX_X4(ah[t][0], ah[t][1], ah[t][2], ah[t][3], stb + aoff[t] + kb);
                LDMATRIX_X4(al[t][0], al[t][1], al[t][2], al[t][3], stb + aoff[t] + ARR_A8 + kb);
            }
            #pragma unroll
            for (int g = 0; g < 2; g++) {
                LDMATRIX_X4(bh[g][0], bh[g][1], bh[g][2], bh[g][3], stb + boff[g] + kb);
                LDMATRIX_X4(bl[g][0], bl[g][1], bl[g][2], bl[g][3], stb + boff[g] + ARR_W8 + kb);
            }
            // hh pass
            #pragma unroll
            for (int t = 0; t < 2; t++)
                #pragma unroll
                for (int g = 0; g < 2; g++) {
                    MMA_S8(acch[t][2 * g],     ah[t], bh[g][0], bh[g][1]);
                    MMA_S8(acch[t][2 * g + 1], ah[t], bh[g][2], bh[g][3]);
                }
            // mid pass: ah*wl + al*wh (same scale 1/256)
            #pragma unroll
            for (int t = 0; t < 2; t++)
                #pragma unroll
                for (int g = 0; g < 2; g++) {
                    MMA_S8(accm[t][2 * g],     ah[t], bl[g][0], bl[g][1]);
                    MMA_S8(accm[t][2 * g + 1], ah[t], bl[g][2], bl[g][3]);
                }
            #pragma unroll
            for (int t = 0; t < 2; t++)
                #pragma unroll
                for (int g = 0; g < 2; g++) {
                    MMA_S8(accm[t][2 * g],     al[t], bh[g][0], bh[g][1]);
                    MMA_S8(accm[t][2 * g + 1], al[t], bh[g][2], bh[g][3]);
                }
        }
    }

    // epilogue
    const float ISC = 1.f / 256.f;
    const int mBase = rowBase + warpM * 32;
    const int nBase = colBase + warpN * 32;
    #pragma unroll
    for (int t = 0; t < 2; t++) {
        const int r0 = mBase + t * 16 + (lane >> 2);
        const float sa0 = __ldg(scaleA + r0);
        const float sa1 = __ldg(scaleA + r0 + 8);
        #pragma unroll
        for (int f = 0; f < 4; f++) {
            const int col = nBase + f * 8 + (lane & 3) * 2;
            const float sw0 = __ldg(scaleW + col);
            const float sw1 = __ldg(scaleW + col + 1);
            const float bv0 = __ldg(bias + col), bv1 = __ldg(bias + col + 1);
            const int* h = acch[t][f];
            const int* m = accm[t][f];
            float v00 = sa0 * sw0 * ((float)h[0] + (float)m[0] * ISC) + bv0;
            float v01 = sa0 * sw1 * ((float)h[1] + (float)m[1] * ISC) + bv1;
            float v10 = sa1 * sw0 * ((float)h[2] + (float)m[2] * ISC) + bv0;
            float v11 = sa1 * sw1 * ((float)h[3] + (float)m[3] * ISC) + bv1;
            if (OUT_MODE == 1) {
                v00 = v00 >= 0.f ? v00 : 0.2f * v00;
                v01 = v01 >= 0.f ? v01 : 0.2f * v01;
                v10 = v10 >= 0.f ? v10 : 0.2f * v10;
                v11 = v11 >= 0.f ? v11 : 0.2f * v11;
            }
            *(float2*)(Cf + (size_t)r0 * N + col)       = make_float2(v00, v01);
            *(float2*)(Cf + (size_t)(r0 + 8) * N + col) = make_float2(v10, v11);
        }
    }
}

// ---------------- LayerNorm + lrelu -> int8 quantize ----------------
template<int NV4>
__global__ __launch_bounds__(256)
void ln_quant_kernel(const float* __restrict__ X, const float* __restrict__ g,
                     const float* __restrict__ b, int8_t* __restrict__ Qh,
                     int8_t* __restrict__ Ql, float* __restrict__ scale) {
    const int H = NV4 * 1024;
    const int tid = threadIdx.x;
    const float* row = X + (size_t)blockIdx.x * H;
    __shared__ float red[8];

    float4 v[NV4];
    float s = 0.f;
    #pragma unroll
    for (int q = 0; q < NV4; q++) {
        v[q] = *(const float4*)(row + (tid + 256 * q) * 4);
        s += v[q].x + v[q].y + v[q].z + v[q].w;
    }
    const float mean = block_reduce_sum(s, red) * (1.f / H);

    float ss = 0.f;
    #pragma unroll
    for (int q = 0; q < NV4; q++) {
        float dx;
        dx = v[q].x - mean; ss += dx * dx;
        dx = v[q].y - mean; ss += dx * dx;
        dx = v[q].z - mean; ss += dx * dx;
        dx = v[q].w - mean; ss += dx * dx;
    }
    const float var  = block_reduce_sum(ss, red) * (1.f / H);
    const float rstd = rsqrtf(var + 1e-5f);

    float yv[NV4][4];
    float mx = 0.f;
    #pragma unroll
    for (int q = 0; q < NV4; q++) {
        const int col = (tid + 256 * q) * 4;
        const float4 g4 = *(const float4*)(g + col);
        const float4 b4 = *(const float4*)(b + col);
        float y0 = (v[q].x - mean) * rstd * g4.x + b4.x; y0 = y0 >= 0.f ? y0 : 0.2f * y0;
        float y1 = (v[q].y - mean) * rstd * g4.y + b4.y; y1 = y1 >= 0.f ? y1 : 0.2f * y1;
        float y2 = (v[q].z - mean) * rstd * g4.z + b4.z; y2 = y2 >= 0.f ? y2 : 0.2f * y2;
        float y3 = (v[q].w - mean) * rstd * g4.w + b4.w; y3 = y3 >= 0.f ? y3 : 0.2f * y3;
        yv[q][0] = y0; yv[q][1] = y1; yv[q][2] = y2; yv[q][3] = y3;
        mx = fmaxf(mx, fmaxf(fmaxf(fabsf(y0), fabsf(y1)), fmaxf(fabsf(y2), fabsf(y3))));
    }
    mx = block_reduce_max(mx, red);
    const float mxg  = fmaxf(mx, 1e-20f);
    const float sa   = mxg * (1.f / 127.f);
    const float inv  = 127.f / mxg;
    const float inv2 = 256.f * 127.f / mxg;
    if (tid == 0) scale[blockIdx.x] = sa;

    int8_t* qh = Qh + (size_t)blockIdx.x * H;
    int8_t* ql = Ql + (size_t)blockIdx.x * H;
    #pragma unroll
    for (int q = 0; q < NV4; q++) {
        const int i4 = tid + 256 * q;
        int8_t h0, l0, h1, l1, h2, l2, h3, l3;
        quant2(yv[q][0], sa, inv, inv2, h0, l0);
        quant2(yv[q][1], sa, inv, inv2, h1, l1);
        quant2(yv[q][2], sa, inv, inv2, h2, l2);
        quant2(yv[q][3], sa, inv, inv2, h3, l3);
        ((char4*)qh)[i4] = make_char4(h0, h1, h2, h3);
        ((char4*)ql)[i4] = make_char4(l0, l1, l2, l3);
    }
}

// ---------------- reparam + context attention -> int8 quantize ----------------
__global__ __launch_bounds__(256)
void reparam_attn_kernel(const float* __restrict__ muv, const float* __restrict__ eps,
                         const float* __restrict__ ctx,
                         float* __restrict__ out_mu, float* __restrict__ out_lv,
                         int8_t* __restrict__ Qh, int8_t* __restrict__ Ql,
                         float* __restrict__ scale) {
    __shared__ float ctxs[M_][L_ + 1];
    __shared__ float zs[8][L_];
    __shared__ float attns[8][M_];

    const int tid = threadIdx.x;
    for (int i = tid; i < M_ * L_; i += 256)
        ctxs[i >> 8][i & 255] = ctx[i];
    __syncthreads();

    const int w    = tid >> 5;
    const int lane = tid & 31;
    const size_t row = (size_t)blockIdx.x * 8 + w;
    const float* mvrow = muv + row * 512;
    const float* eprow = eps + row * L_;

    #pragma unroll
    for (int i = 0; i < 8; i++) {
        const int j = lane + 32 * i;
        const float mu = mvrow[j], lv = mvrow[256 + j];
        out_mu[row * L_ + j] = mu;
        out_lv[row * L_ + j] = lv;
        zs[w][j] = mu + eprow[j] * expf(0.5f * lv);
    }
    __syncwarp();

    float s = 0.f;
    #pragma unroll 8
    for (int j = 0; j < L_; j++)
        s = fmaf(zs[w][j], ctxs[lane][j], s);

    float mxs = s;
    #pragma unroll
    for (int o = 16; o; o >>= 1) mxs = fmaxf(mxs, __shfl_xor_sync(0xffffffffu, mxs, o));
    float e = expf(s - mxs);
    float tot = e;
    #pragma unroll
    for (int o = 16; o; o >>= 1) tot += __shfl_xor_sync(0xffffffffu, tot, o);
    attns[w][lane] = e / tot;
    __syncwarp();

    float vv[8];
    float lm = 0.f;
    #pragma unroll
    for (int i = 0; i < 8; i++) {
        const int j = lane + 32 * i;
        float add = 0.f;
        #pragma unroll
        for (int m = 0; m < M_; m++)
            add = fmaf(attns[w][m], ctxs[m][j], add);
        vv[i] = zs[w][j] + 0.1f * add;
        lm = fmaxf(lm, fabsf(vv[i]));
    }
    #pragma unroll
    for (int o = 16; o; o >>= 1) lm = fmaxf(lm, __shfl_xor_sync(0xffffffffu, lm, o));
    const float mxg  = fmaxf(lm, 1e-20f);
    const float sa   = mxg * (1.f / 127.f);
    const float inv  = 127.f / mxg;
    const float inv2 = 256.f * 127.f / mxg;
    if (lane == 0) scale[row] = sa;

    int8_t* qh = Qh + row * L_;
    int8_t* ql = Ql + row * L_;
    #pragma unroll
    for (int i = 0; i < 8; i++) {
        const int j = lane + 32 * i;
        int8_t h, l;
        quant2(vv[i], sa, inv, inv2, h, l);
        qh[j] = h; ql[j] = l;
    }
}

// ---------------------------------------------------------------------------
extern "C" void kernel_launch(void* const* d_in, const int* in_sizes, int n_in,
                              void* d_out, int out_size) {
    (void)in_sizes; (void)n_in; (void)out_size;
    const float* x      = (const float*)d_in[0];
    const float* eps    = (const float*)d_in[1];
    const float* enc_w1 = (const float*)d_in[2];
    const float* enc_b1 = (const float*)d_in[3];
    const float* ln1_g  = (const float*)d_in[4];
    const float* ln1_b  = (const float*)d_in[5];
    const float* enc_w2 = (const float*)d_in[6];
    const float* enc_b2 = (const float*)d_in[7];
    const float* ln2_g  = (const float*)d_in[8];
    const float* ln2_b  = (const float*)d_in[9];
    const float* mu_w   = (const float*)d_in[10];
    const float* mu_b   = (const float*)d_in[11];
    const float* lv_w   = (const float*)d_in[12];
    const float* lv_b   = (const float*)d_in[13];
    const float* di_w   = (const float*)d_in[14];
    const float* di_b   = (const float*)d_in[15];
    const float* dec_w1 = (const float*)d_in[16];
    const float* dec_b1 = (const float*)d_in[17];
    const float* dln1_g = (const float*)d_in[18];
    const float* dln1_b = (const float*)d_in[19];
    const float* dec_w2 = (const float*)d_in[20];
    const float* dec_b2 = (const float*)d_in[21];
    const float* dln2_g = (const float*)d_in[22];
    const float* dln2_b = (const float*)d_in[23];
    const float* dec_w3 = (const float*)d_in[24];
    const float* dec_b3 = (const float*)d_in[25];
    const float* ctx    = (const float*)d_in[26];

    float* out     = (float*)d_out;
    float* out_rec = out;
    float* out_mu  = out + (size_t)B_ * D_;
    float* out_lv  = out_mu + (size_t)B_ * L_;

    int8_t *wqh, *wql, *q1h, *q1l, *q2h, *q2l;
    float *f32buf, *sa1, *sa2, *ws, *bias512;
    cudaGetSymbolAddress((void**)&wqh, g_wqh);
    cudaGetSymbolAddress((void**)&wql, g_wql);
    cudaGetSymbolAddress((void**)&q1h, g_q1h);
    cudaGetSymbolAddress((void**)&q1l, g_q1l);
    cudaGetSymbolAddress((void**)&q2h, g_q2h);
    cudaGetSymbolAddress((void**)&q2l, g_q2l);
    cudaGetSymbolAddress((void**)&f32buf, g_f32);
    cudaGetSymbolAddress((void**)&sa1, g_sa1);
    cudaGetSymbolAddress((void**)&sa2, g_sa2);
    cudaGetSymbolAddress((void**)&ws, g_ws);
    cudaGetSymbolAddress((void**)&bias512, g_bias512);

    cudaFuncSetAttribute(imma_gemm_kernel<0>, cudaFuncAttributeMaxDynamicSharedMemorySize, GSMEM);
    cudaFuncSetAttribute(imma_gemm_kernel<1>, cudaFuncAttributeMaxDynamicSharedMemorySize, GSMEM);

    // weight element offsets (same packing as before; mu|lv contiguous)
    const size_t o_e1 = 0,       o_e2 = 786432,  o_mu = 1835008, o_lv = 2097152;
    const size_t o_di = 2359296, o_d1 = 2621440, o_d2 = 3670016, o_d3 = 5767168;
    // weight scale row offsets
    const size_t s_e1 = 0, s_e2 = 1024, s_mu = 2048, s_lv = 2304;
    const size_t s_di = 2560, s_d1 = 3584, s_d2 = 4608, s_d3 = 6656;

    cudaMemcpyAsync(bias512,       mu_b, 256 * sizeof(float), cudaMemcpyDeviceToDevice);
    cudaMemcpyAsync(bias512 + 256, lv_b, 256 * sizeof(float), cudaMemcpyDeviceToDevice);

    const dim3 blk(256);
    auto quantW = [&](const float* w, size_t wo, size_t so, int rows, int K) {
        quant_rows_kernel<<<rows, blk>>>(w, wqh + wo, wql + wo, ws + so, K);
    };

    // quantize input + all weights
    quant_rows_kernel<<<B_, blk>>>(x, q1h, q1l, sa1, D_);
    quantW(enc_w1, o_e1, s_e1, H_, D_);
    quantW(enc_w2, o_e2, s_e2, H_, H_);
    quantW(mu_w,   o_mu, s_mu, L_, H_);
    quantW(lv_w,   o_lv, s_lv, L_, H_);
    quantW(di_w,   o_di, s_di, H_, L_);
    quantW(dec_w1, o_d1, s_d1, H_, H_);
    quantW(dec_w2, o_d2, s_d2, 2 * H_, H_);
    quantW(dec_w3, o_d3, s_d3, D_, 2 * H_);

    auto gemm = [&](int mode, const int8_t* ah, const int8_t* al, const float* sca,
                    size_t wo, size_t so, const float* bias, float* cf, int N, int K) {
        dim3 g(N / 128, B_ / 64);
        if (mode == 0)
            imma_gemm_kernel<0><<<g, blk, GSMEM>>>(ah, al, sca, wqh + wo, wql + wo,
                                                   ws + so, bias, cf, N, K);
        else
            imma_gemm_kernel<1><<<g, blk, GSMEM>>>(ah, al, sca, wqh + wo, wql + wo,
                                                   ws + so, bias, cf, N, K);
    };

    // encoder
    gemm(0, q1h, q1l, sa1, o_e1, s_e1, enc_b1, f32buf, H_, D_);
    ln_quant_kernel<1><<<B_, blk>>>(f32buf, ln1_g, ln1_b, q2h, q2l, sa2);
    gemm(0, q2h, q2l, sa2, o_e2, s_e2, enc_b2, f32buf, H_, H_);
    ln_quant_kernel<1><<<B_, blk>>>(f32buf, ln2_g, ln2_b, q1h, q1l, sa1);
    // merged mu|lv GEMM -> f32buf [B, 512]
    gemm(0, q1h, q1l, sa1, o_mu, s_mu, bias512, f32buf, 512, H_);
    reparam_attn_kernel<<<B_ / 8, blk>>>(f32buf, eps, ctx, out_mu, out_lv, q2h, q2l, sa2);
    // decoder
    gemm(1, q2h, q2l, sa2, o_di, s_di, di_b, f32buf, H_, L_);           // lrelu in epilogue
    quant_rows_kernel<<<B_, blk>>>(f32buf, q1h, q1l, sa1, H_);
    gemm(0, q1h, q1l, sa1, o_d1, s_d1, dec_b1, f32buf, H_, H_);
    ln_quant_kernel<1><<<B_, blk>>>(f32buf, dln1_g, dln1_b, q2h, q2l, sa2);
    gemm(0, q2h, q2l, sa2, o_d2, s_d2, dec_b2, f32buf, 2 * H_, H_);
    ln_quant_kernel<2><<<B_, blk>>>(f32buf, dln2_g, dln2_b, q1h, q1l, sa1);
    gemm(0, q1h, q1l, sa1, o_d3, s_d3, dec_b3, out_rec, D_, 2 * H_);
}

// round 15
// speedup vs baseline: 2.4513x; 2.4513x over previous
#include <cuda_runtime.h>
#include <cuda_bf16.h>
#include <cstdint>
#include <math.h>

#define B_  32768
#define D_  768
#define H_  1024
#define L_  256
#define M_  32

// ---------------- helpers ----------------
__device__ __forceinline__ uint32_t smem_to_u32(const void* p) {
    uint32_t a;
    asm("{ .reg .u64 t; cvta.to.shared.u64 t, %1; cvt.u32.u64 %0, t; }" : "=r"(a) : "l"(p));
    return a;
}
__device__ __forceinline__ void cp16(uint32_t dst, const void* src) {
    asm volatile("cp.async.cg.shared.global [%0], [%1], 16;\n" :: "r"(dst), "l"(src) : "memory");
}
#define CP_COMMIT()  asm volatile("cp.async.commit_group;\n" ::: "memory")
#define CP_WAIT(n)   asm volatile("cp.async.wait_group %0;\n" :: "n"(n) : "memory")
#define LDMATRIX_X4(r0, r1, r2, r3, addr) \
    asm volatile("ldmatrix.sync.aligned.m8n8.x4.shared.b16 {%0,%1,%2,%3}, [%4];" \
                 : "=r"(r0), "=r"(r1), "=r"(r2), "=r"(r3) : "r"(addr))
#define MMA_BF16(d, a, b0, b1) \
    asm volatile("mma.sync.aligned.m16n8k16.row.col.f32.bf16.bf16.f32 " \
                 "{%0,%1,%2,%3}, {%4,%5,%6,%7}, {%8,%9}, {%0,%1,%2,%3};" \
                 : "+f"((d)[0]), "+f"((d)[1]), "+f"((d)[2]), "+f"((d)[3]) \
                 : "r"((a)[0]), "r"((a)[1]), "r"((a)[2]), "r"((a)[3]), "r"(b0), "r"(b1))

// ---------------- scratch ----------------
#define WTOT 7340032
#define PMAX ((size_t)B_ * 2 * H_)
__device__ __nv_bfloat16 g_wh[WTOT], g_wl[WTOT];
__device__ __nv_bfloat16 g_p1h[PMAX], g_p1l[PMAX], g_p2h[PMAX], g_p2l[PMAX];
__device__ float g_f32[PMAX];
__device__ float g_bias512[512];

__device__ __forceinline__ void split2(float v, __nv_bfloat16& h, __nv_bfloat16& l) {
    h = __float2bfloat16(v);
    l = __float2bfloat16(v - __bfloat162float(h));
}

// ---------------- batched fp32 -> (hi,lo) bf16 split ----------------
// One launch covers input x + all 8 weight matrices (9 segments).
struct SplitJobs {
    const float*   src[9];
    __nv_bfloat16* dh[9];
    __nv_bfloat16* dl[9];
    long           end[9];   // inclusive prefix sums of n4 (float4 chunks)
};

__global__ __launch_bounds__(256)
void split_batched_kernel(SplitJobs jobs, long total4) {
    long i = (long)blockIdx.x * 256 + threadIdx.x;
    if (i >= total4) return;
    int seg = 0;
    #pragma unroll
    for (int s = 0; s < 9; s++) seg += (i >= jobs.end[s]) ? 1 : 0;
    const long base = (seg == 0) ? 0 : jobs.end[seg - 1];
    const long k = i - base;

    float4 v = ((const float4*)jobs.src[seg])[k];
    __nv_bfloat16 h0, l0, h1, l1, h2, l2, h3, l3;
    split2(v.x, h0, l0); split2(v.y, h1, l1); split2(v.z, h2, l2); split2(v.w, h3, l3);
    ((__nv_bfloat162*)jobs.dh[seg])[k * 2]     = __halves2bfloat162(h0, h1);
    ((__nv_bfloat162*)jobs.dh[seg])[k * 2 + 1] = __halves2bfloat162(h2, h3);
    ((__nv_bfloat162*)jobs.dl[seg])[k * 2]     = __halves2bfloat162(l0, l1);
    ((__nv_bfloat162*)jobs.dl[seg])[k * 2 + 1] = __halves2bfloat162(l2, l3);
}

// ---------------- split-bf16 GEMM via mma.sync (HMMA) ----------------
// C[B,N] = A[B,K] @ W[N,K]^T + bias; acc += Ah*Wh + Ah*Wl + Al*Wh (fp32 acc).
// CTA 128x128, BK=32, 256 threads, warp tile 64x32 (warps 2m x 4n).
// 2-stage cp.async pipeline, single __syncthreads per ktile (fill issued
// after the sync, overlapping the MMA phase). 80KB smem -> 2 CTAs/SM.
#define ARR_A   10240           // 128 * 80
#define ARR_W   10240           // 128 * 80
#define AW_OFF  (2 * ARR_A)
#define STAGE_B (2 * ARR_A + 2 * ARR_W)   // 40960
#define GSMEM   (2 * STAGE_B)             // 81920

template<int OUT_MODE>
__global__ void __launch_bounds__(256, 2)
mma_gemm_kernel(const __nv_bfloat16* __restrict__ Ah, const __nv_bfloat16* __restrict__ Al,
                const __nv_bfloat16* __restrict__ Wh, const __nv_bfloat16* __restrict__ Wl,
                const float* __restrict__ bias, float* __restrict__ Cf,
                __nv_bfloat16* __restrict__ Oh, __nv_bfloat16* __restrict__ Ol,
                int N, int K) {
    extern __shared__ char smem[];
    const uint32_t smem_u = smem_to_u32(smem);
    const int tid  = threadIdx.x;
    const int wid  = tid >> 5, lane = tid & 31;
    const int rowBase = blockIdx.y * 128;
    const int colBase = blockIdx.x * 128;
    const int warpM = wid & 1;      // 0..1  -> 64 rows
    const int warpN = wid >> 1;     // 0..3  -> 32 cols

    float acc[4][4][4];
    #pragma unroll
    for (int t = 0; t < 4; t++)
        #pragma unroll
        for (int f = 0; f < 4; f++)
            #pragma unroll
            for (int e = 0; e < 4; e++) acc[t][f][e] = 0.f;

    uint32_t aoff[4];
    #pragma unroll
    for (int t = 0; t < 4; t++)
        aoff[t] = (uint32_t)((warpM * 64 + t * 16 + (lane & 15)) * 80 + ((lane >> 4) << 4));
    uint32_t boff[2];
    #pragma unroll
    for (int g = 0; g < 2; g++) {
        int n = warpN * 32 + g * 16 + (lane & 7) + ((lane & 16) ? 8 : 0);
        boff[g] = (uint32_t)(AW_OFF + n * 80 + ((lane & 8) ? 16 : 0));
    }

    const int ktiles = K >> 5;

    auto fill = [&](int s, int kt) {
        const uint32_t stb = smem_u + s * STAGE_B;
        #pragma unroll
        for (int it = 0; it < 4; it++) {
            int idx = it * 256 + tid;
            int arr = idx >> 9;
            int r   = (idx >> 2) & 127;
            int c   = idx & 3;
            const __nv_bfloat16* src =
                (arr ? Al : Ah) + (size_t)(rowBase + r) * K + kt * 32 + c * 8;
            cp16(stb + arr * ARR_A + r * 80 + c * 16, src);
        }
        #pragma unroll
        for (int it = 0; it < 4; it++) {
            int idx = it * 256 + tid;
            int arr = idx >> 9;
            int r   = (idx >> 2) & 127;
            int c   = idx & 3;
            const __nv_bfloat16* src =
                (arr ? Wl : Wh) + (size_t)(colBase + r) * K + kt * 32 + c * 8;
            cp16(stb + AW_OFF + arr * ARR_W + r * 80 + c * 16, src);
        }
        CP_COMMIT();
    };

    fill(0, 0);
    for (int kt = 0; kt < ktiles; kt++) {
        const int s = kt & 1;
        CP_WAIT(0);
        __syncthreads();                       // single barrier per ktile
        if (kt + 1 < ktiles) fill(s ^ 1, kt + 1);   // overlaps MMAs below

        const uint32_t stb = smem_u + s * STAGE_B;
        #pragma unroll
        for (int kc = 0; kc < 2; kc++) {
            const uint32_t kb = kc * 32;
            uint32_t ah[4][4], al[4][4], bh[2][4], bl[2][4];
            #pragma unroll
            for (int t = 0; t < 4; t++) {
                LDMATRIX_X4(ah[t][0], ah[t][1], ah[t][2], ah[t][3], stb + aoff[t] + kb);
                LDMATRIX_X4(al[t][0], al[t][1], al[t][2], al[t][3], stb + aoff[t] + ARR_A + kb);
            }
            #pragma unroll
            for (int g = 0; g < 2; g++) {
                LDMATRIX_X4(bh[g][0], bh[g][1], bh[g][2], bh[g][3], stb + boff[g] + kb);
                LDMATRIX_X4(bl[g][0], bl[g][1], bl[g][2], bl[g][3], stb + boff[g] + ARR_W + kb);
            }
            #pragma unroll
            for (int t = 0; t < 4; t++)
                #pragma unroll
                for (int g = 0; g < 2; g++) {
                    MMA_BF16(acc[t][2 * g],     ah[t], bh[g][0], bh[g][1]);
                    MMA_BF16(acc[t][2 * g + 1], ah[t], bh[g][2], bh[g][3]);
                }
            #pragma unroll
            for (int t = 0; t < 4; t++)
                #pragma unroll
                for (int g = 0; g < 2; g++) {
                    MMA_BF16(acc[t][2 * g],     ah[t], bl[g][0], bl[g][1]);
                    MMA_BF16(acc[t][2 * g + 1], ah[t], bl[g][2], bl[g][3]);
                }
            #pragma unroll
            for (int t = 0; t < 4; t++)
                #pragma unroll
                for (int g = 0; g < 2; g++) {
                    MMA_BF16(acc[t][2 * g],     al[t], bh[g][0], bh[g][1]);
                    MMA_BF16(acc[t][2 * g + 1], al[t], bh[g][2], bh[g][3]);
                }
        }
    }

    // epilogue
    const int mBase = rowBase + warpM * 64;
    const int nBase = colBase + warpN * 32;
    #pragma unroll
    for (int t = 0; t < 4; t++) {
        #pragma unroll
        for (int f = 0; f < 4; f++) {
            const int col = nBase + f * 8 + (lane & 3) * 2;
            const int r0  = mBase + t * 16 + (lane >> 2);
            const float bv0 = __ldg(bias + col), bv1 = __ldg(bias + col + 1);
            float v00 = acc[t][f][0] + bv0, v01 = acc[t][f][1] + bv1;
            float v10 = acc[t][f][2] + bv0, v11 = acc[t][f][3] + bv1;
            if (OUT_MODE == 0) {
                *(float2*)(Cf + (size_t)r0 * N + col)       = make_float2(v00, v01);
                *(float2*)(Cf + (size_t)(r0 + 8) * N + col) = make_float2(v10, v11);
            } else {
                v00 = v00 >= 0.f ? v00 : 0.2f * v00;
                v01 = v01 >= 0.f ? v01 : 0.2f * v01;
                v10 = v10 >= 0.f ? v10 : 0.2f * v10;
                v11 = v11 >= 0.f ? v11 : 0.2f * v11;
                __nv_bfloat16 h0, l0, h1, l1;
                split2(v00, h0, l0); split2(v01, h1, l1);
                *(__nv_bfloat162*)(Oh + (size_t)r0 * N + col) = __halves2bfloat162(h0, h1);
                *(__nv_bfloat162*)(Ol + (size_t)r0 * N + col) = __halves2bfloat162(l0, l1);
                split2(v10, h0, l0); split2(v11, h1, l1);
                *(__nv_bfloat162*)(Oh + (size_t)(r0 + 8) * N + col) = __halves2bfloat162(h0, h1);
                *(__nv_bfloat162*)(Ol + (size_t)(r0 + 8) * N + col) = __halves2bfloat162(l0, l1);
            }
        }
    }
}

// ---------------- LayerNorm + lrelu -> split-bf16 ----------------
__device__ __forceinline__ float block_reduce_sum(float val, float* red) {
    const int lane = threadIdx.x & 31;
    const int w    = threadIdx.x >> 5;
    #pragma unroll
    for (int o = 16; o; o >>= 1) val += __shfl_xor_sync(0xffffffffu, val, o);
    if (lane == 0) red[w] = val;
    __syncthreads();
    float t = (lane < 8) ? red[lane] : 0.f;
    if (w == 0) {
        #pragma unroll
        for (int o = 4; o; o >>= 1) t += __shfl_xor_sync(0xffffffffu, t, o);
        if (lane == 0) red[0] = t;
    }
    __syncthreads();
    float r = red[0];
    __syncthreads();
    return r;
}

template<int NV4>
__global__ __launch_bounds__(256)
void ln_split_kernel(const float* __restrict__ X, const float* __restrict__ g,
                     const float* __restrict__ b, __nv_bfloat16* __restrict__ Oh,
                     __nv_bfloat16* __restrict__ Ol) {
    const int H = NV4 * 1024;
    const int tid = threadIdx.x;
    const float* row = X + (size_t)blockIdx.x * H;
    __shared__ float red[8];

    float4 v[NV4];
    float s = 0.f;
    #pragma unroll
    for (int q = 0; q < NV4; q++) {
        v[q] = *(const float4*)(row + (tid + 256 * q) * 4);
        s += v[q].x + v[q].y + v[q].z + v[q].w;
    }
    const float mean = block_reduce_sum(s, red) * (1.f / H);

    float ss = 0.f;
    #pragma unroll
    for (int q = 0; q < NV4; q++) {
        float dx;
        dx = v[q].x - mean; ss += dx * dx;
        dx = v[q].y - mean; ss += dx * dx;
        dx = v[q].z - mean; ss += dx * dx;
        dx = v[q].w - mean; ss += dx * dx;
    }
    const float var  = block_reduce_sum(ss, red) * (1.f / H);
    const float rstd = rsqrtf(var + 1e-5f);

    __nv_bfloat16* oh = Oh + (size_t)blockIdx.x * H;
    __nv_bfloat16* ol = Ol + (size_t)blockIdx.x * H;
    #pragma unroll
    for (int q = 0; q < NV4; q++) {
        const int col = (tid + 256 * q) * 4;
        const float4 g4 = *(const float4*)(g + col);
        const float4 b4 = *(const float4*)(b + col);
        float y0 = (v[q].x - mean) * rstd * g4.x + b4.x; y0 = y0 >= 0.f ? y0 : 0.2f * y0;
        float y1 = (v[q].y - mean) * rstd * g4.y + b4.y; y1 = y1 >= 0.f ? y1 : 0.2f * y1;
        float y2 = (v[q].z - mean) * rstd * g4.z + b4.z; y2 = y2 >= 0.f ? y2 : 0.2f * y2;
        float y3 = (v[q].w - mean) * rstd * g4.w + b4.w; y3 = y3 >= 0.f ? y3 : 0.2f * y3;
        __nv_bfloat16 h0, l0, h1, l1, h2, l2, h3, l3;
        split2(y0, h0, l0); split2(y1, h1, l1); split2(y2, h2, l2); split2(y3, h3, l3);
        *(__nv_bfloat162*)(oh + col)     = __halves2bfloat162(h0, h1);
        *(__nv_bfloat162*)(oh + col + 2) = __halves2bfloat162(h2, h3);
        *(__nv_bfloat162*)(ol + col)     = __halves2bfloat162(l0, l1);
        *(__nv_bfloat162*)(ol + col + 2) = __halves2bfloat162(l2, l3);
    }
}

// ---------------- reparam + context attention -> split-bf16 ----------------
__global__ __launch_bounds__(256)
void reparam_attn_kernel(const float* __restrict__ muv, const float* __restrict__ eps,
                         const float* __restrict__ ctx,
                         float* __restrict__ out_mu, float* __restrict__ out_lv,
                         __nv_bfloat16* __restrict__ Zh, __nv_bfloat16* __restrict__ Zl) {
    __shared__ float ctxs[M_][L_ + 1];
    __shared__ float zs[8][L_];
    __shared__ float attns[8][M_];

    const int tid = threadIdx.x;
    for (int i = tid; i < M_ * L_; i += 256)
        ctxs[i >> 8][i & 255] = ctx[i];
    __syncthreads();

    const int w    = tid >> 5;
    const int lane = tid & 31;
    const size_t row = (size_t)blockIdx.x * 8 + w;
    const float* mvrow = muv + row * 512;
    const float* eprow = eps + row * L_;

    #pragma unroll
    for (int i = 0; i < 8; i++) {
        const int j = lane + 32 * i;
        const float mu = mvrow[j], lv = mvrow[256 + j];
        out_mu[row * L_ + j] = mu;
        out_lv[row * L_ + j] = lv;
        zs[w][j] = mu + eprow[j] * expf(0.5f * lv);
    }
    __syncwarp();

    float s = 0.f;
    #pragma unroll 8
    for (int j = 0; j < L_; j++)
        s = fmaf(zs[w][j], ctxs[lane][j], s);

    float mx = s;
    #pragma unroll
    for (int o = 16; o; o >>= 1) mx = fmaxf(mx, __shfl_xor_sync(0xffffffffu, mx, o));
    float e = expf(s - mx);
    float tot = e;
    #pragma unroll
    for (int o = 16; o; o >>= 1) tot += __shfl_xor_sync(0xffffffffu, tot, o);
    attns[w][lane] = e / tot;
    __syncwarp();

    __nv_bfloat16* zh = Zh + row * L_;
    __nv_bfloat16* zl = Zl + row * L_;
    #pragma unroll
    for (int i = 0; i < 8; i++) {
        const int j = lane + 32 * i;
        float add = 0.f;
        #pragma unroll
        for (int m = 0; m < M_; m++)
            add = fmaf(attns[w][m], ctxs[m][j], add);
        float v = zs[w][j] + 0.1f * add;
        __nv_bfloat16 h, l;
        split2(v, h, l);
        zh[j] = h; zl[j] = l;
    }
}

// ---------------------------------------------------------------------------
extern "C" void kernel_launch(void* const* d_in, const int* in_sizes, int n_in,
                              void* d_out, int out_size) {
    (void)in_sizes; (void)n_in; (void)out_size;
    const float* x      = (const float*)d_in[0];
    const float* eps    = (const float*)d_in[1];
    const float* enc_w1 = (const float*)d_in[2];
    const float* enc_b1 = (const float*)d_in[3];
    const float* ln1_g  = (const float*)d_in[4];
    const float* ln1_b  = (const float*)d_in[5];
    const float* enc_w2 = (const float*)d_in[6];
    const float* enc_b2 = (const float*)d_in[7];
    const float* ln2_g  = (const float*)d_in[8];
    const float* ln2_b  = (const float*)d_in[9];
    const float* mu_w   = (const float*)d_in[10];
    const float* mu_b   = (const float*)d_in[11];
    const float* lv_w   = (const float*)d_in[12];
    const float* lv_b   = (const float*)d_in[13];
    const float* di_w   = (const float*)d_in[14];
    const float* di_b   = (const float*)d_in[15];
    const float* dec_w1 = (const float*)d_in[16];
    const float* dec_b1 = (const float*)d_in[17];
    const float* dln1_g = (const float*)d_in[18];
    const float* dln1_b = (const float*)d_in[19];
    const float* dec_w2 = (const float*)d_in[20];
    const float* dec_b2 = (const float*)d_in[21];
    const float* dln2_g = (const float*)d_in[22];
    const float* dln2_b = (const float*)d_in[23];
    const float* dec_w3 = (const float*)d_in[24];
    const float* dec_b3 = (const float*)d_in[25];
    const float* ctx    = (const float*)d_in[26];

    float* out     = (float*)d_out;
    float* out_rec = out;
    float* out_mu  = out + (size_t)B_ * D_;
    float* out_lv  = out_mu + (size_t)B_ * L_;

    __nv_bfloat16 *wh, *wl, *p1h, *p1l, *p2h, *p2l;
    float *f32buf, *bias512;
    cudaGetSymbolAddress((void**)&wh, g_wh);
    cudaGetSymbolAddress((void**)&wl, g_wl);
    cudaGetSymbolAddress((void**)&p1h, g_p1h);
    cudaGetSymbolAddress((void**)&p1l, g_p1l);
    cudaGetSymbolAddress((void**)&p2h, g_p2h);
    cudaGetSymbolAddress((void**)&p2l, g_p2l);
    cudaGetSymbolAddress((void**)&f32buf, g_f32);
    cudaGetSymbolAddress((void**)&bias512, g_bias512);

    cudaFuncSetAttribute(mma_gemm_kernel<0>, cudaFuncAttributeMaxDynamicSharedMemorySize, GSMEM);
    cudaFuncSetAttribute(mma_gemm_kernel<1>, cudaFuncAttributeMaxDynamicSharedMemorySize, GSMEM);

    const size_t o_e1 = 0,       o_e2 = 786432,  o_mu = 1835008, o_lv = 2097152;
    const size_t o_di = 2359296, o_d1 = 2621440, o_d2 = 3670016, o_d3 = 5767168;

    cudaMemcpyAsync(bias512,       mu_b, 256 * sizeof(float), cudaMemcpyDeviceToDevice);
    cudaMemcpyAsync(bias512 + 256, lv_b, 256 * sizeof(float), cudaMemcpyDeviceToDevice);

    const dim3 blk(256);

    // one batched split launch: input x + all 8 weight matrices
    {
        SplitJobs J;
        const float* srcs[9]   = {x, enc_w1, enc_w2, mu_w, lv_w, di_w, dec_w1, dec_w2, dec_w3};
        const size_t offs[9]   = {0, o_e1, o_e2, o_mu, o_lv, o_di, o_d1, o_d2, o_d3};
        const size_t counts[9] = {(size_t)B_ * D_, (size_t)H_ * D_, (size_t)H_ * H_,
                                  (size_t)L_ * H_, (size_t)L_ * H_, (size_t)H_ * L_,
                                  (size_t)H_ * H_, (size_t)2 * H_ * H_, (size_t)D_ * 2 * H_};
        long acc = 0;
        for (int s = 0; s < 9; s++) {
            J.src[s] = srcs[s];
            J.dh[s]  = (s == 0) ? p1h : wh + offs[s];
            J.dl[s]  = (s == 0) ? p1l : wl + offs[s];
            acc += (long)(counts[s] / 4);
            J.end[s] = acc;
        }
        split_batched_kernel<<<(unsigned)((acc + 255) / 256), blk>>>(J, acc);
    }

    auto gemm = [&](int mode, const __nv_bfloat16* ah, const __nv_bfloat16* al,
                    size_t wo, const float* bias, float* cf,
                    __nv_bfloat16* oh, __nv_bfloat16* ol, int N, int K) {
        dim3 g(N / 128, B_ / 128);
        if (mode == 0)
            mma_gemm_kernel<0><<<g, blk, GSMEM>>>(ah, al, wh + wo, wl + wo, bias, cf, oh, ol, N, K);
        else
            mma_gemm_kernel<1><<<g, blk, GSMEM>>>(ah, al, wh + wo, wl + wo, bias, cf, oh, ol, N, K);
    };

    // encoder
    gemm(0, p1h, p1l, o_e1, enc_b1, f32buf, nullptr, nullptr, H_, D_);
    ln_split_kernel<1><<<B_, blk>>>(f32buf, ln1_g, ln1_b, p2h, p2l);
    gemm(0, p2h, p2l, o_e2, enc_b2, f32buf, nullptr, nullptr, H_, H_);
    ln_split_kernel<1><<<B_, blk>>>(f32buf, ln2_g, ln2_b, p1h, p1l);
    // merged mu|lv GEMM -> f32buf [B, 512]
    gemm(0, p1h, p1l, o_mu, bias512, f32buf, nullptr, nullptr, 512, H_);
    reparam_attn_kernel<<<B_ / 8, blk>>>(f32buf, eps, ctx, out_mu, out_lv, p2h, p2l);
    // decoder
    gemm(1, p2h, p2l, o_di, di_b, nullptr, p1h, p1l, H_, L_);
    gemm(0, p1h, p1l, o_d1, dec_b1, f32buf, nullptr, nullptr, H_, H_);
    ln_split_kernel<1><<<B_, blk>>>(f32buf, dln1_g, dln1_b, p2h, p2l);
    gemm(0, p2h, p2l, o_d2, dec_b2, f32buf, nullptr, nullptr, 2 * H_, H_);
    ln_split_kernel<2><<<B_, blk>>>(f32buf, dln2_g, dln2_b, p1h, p1l);
    gemm(0, p1h, p1l, o_d3, dec_b3, out_rec, nullptr, nullptr, D_, 2 * H_);
}